// round 3
// baseline (speedup 1.0000x reference)
#include <cuda_runtime.h>

// Problem constants
#define EMB   1024
#define SEQ   1024
#define BATCH 32
#define FFD   1024
#define NROWS (BATCH*SEQ)            // 32768
#define NELEM ((size_t)NROWS*EMB)    // 33554432
#define NSS   ((size_t)BATCH*SEQ*SEQ)// 33554432

// Scratch (allocation-free per harness rules)
__device__ float g_x[NELEM];   // running residual stream
__device__ float g_h[NELEM];   // LN output / attn result
__device__ float g_q[NELEM];   // q, later x2
__device__ float g_k[NELEM];   // k, later ff1 output
__device__ float g_v[NELEM];   // v

// ---------------------------------------------------------------------------
// x1 = 32*x + pe  (pe broadcast over batch)
// ---------------------------------------------------------------------------
__global__ __launch_bounds__(256) void embed_k(const float* __restrict__ x,
                                               const float* __restrict__ pe,
                                               float* __restrict__ o) {
    size_t i = (size_t)blockIdx.x * blockDim.x + threadIdx.x;  // float4 index
    const float4 a = ((const float4*)x)[i];
    const float4 p = ((const float4*)pe)[i & ((size_t)SEQ * EMB / 4 - 1)];
    float4 r;
    r.x = 32.f * a.x + p.x;
    r.y = 32.f * a.y + p.y;
    r.z = 32.f * a.z + p.z;
    r.w = 32.f * a.w + p.w;
    ((float4*)o)[i] = r;
}

// ---------------------------------------------------------------------------
// LayerNorm over last dim (1024). One block (256 thr) per row.
// ---------------------------------------------------------------------------
__global__ __launch_bounds__(256) void ln_k(const float* __restrict__ in,
                                            const float* __restrict__ g,
                                            const float* __restrict__ b,
                                            float* __restrict__ out) {
    const size_t row = blockIdx.x;
    const int t = threadIdx.x;
    const float4 v = ((const float4*)(in + row * EMB))[t];
    float s  = v.x + v.y + v.z + v.w;
    float ss = v.x * v.x + v.y * v.y + v.z * v.z + v.w * v.w;
#pragma unroll
    for (int o = 16; o > 0; o >>= 1) {
        s  += __shfl_xor_sync(0xFFFFFFFFu, s, o);
        ss += __shfl_xor_sync(0xFFFFFFFFu, ss, o);
    }
    __shared__ float sh_s[8], sh_ss[8];
    if ((t & 31) == 0) { sh_s[t >> 5] = s; sh_ss[t >> 5] = ss; }
    __syncthreads();
    float ts = 0.f, tss = 0.f;
#pragma unroll
    for (int i = 0; i < 8; i++) { ts += sh_s[i]; tss += sh_ss[i]; }
    const float mu  = ts * (1.f / EMB);
    const float var = tss * (1.f / EMB) - mu * mu;
    const float inv = rsqrtf(var + 1e-5f);
    const float4 gg = ((const float4*)g)[t];
    const float4 bb = ((const float4*)b)[t];
    float4 r;
    r.x = (v.x - mu) * inv * gg.x + bb.x;
    r.y = (v.y - mu) * inv * gg.y + bb.y;
    r.z = (v.z - mu) * inv * gg.z + bb.z;
    r.w = (v.w - mu) * inv * gg.w + bb.w;
    ((float4*)(out + row * EMB))[t] = r;
}

// ---------------------------------------------------------------------------
// C = alpha*(A @ W^T) [+bias] [+Rsd] [relu].  A:[M,K] rm, W:[N,K] rm.
// 64x64 tile, BK=16, 256 threads, 4x4 per thread. Batched via gridDim.z.
// ---------------------------------------------------------------------------
__global__ __launch_bounds__(256) void gemm_bt_k(
    const float* __restrict__ A, const float* __restrict__ W,
    const float* __restrict__ bias, const float* __restrict__ Rsd,
    float* __restrict__ C, int N, int K,
    size_t sA, size_t sW, size_t sC, float alpha, int relu)
{
    __shared__ float As[16][64];
    __shared__ float Ws[16][64];
    const int tid = threadIdx.x;
    const int tx = tid & 15, ty = tid >> 4;
    const int bm = blockIdx.y * 64, bn = blockIdx.x * 64;
    const float* Ab = A + (size_t)blockIdx.z * sA;
    const float* Wb = W + (size_t)blockIdx.z * sW;
    float* Cb = C + (size_t)blockIdx.z * sC;

    const int lr = tid >> 2, lc = (tid & 3) << 2;
    const float* ag = Ab + (size_t)(bm + lr) * K + lc;
    const float* wg = Wb + (size_t)(bn + lr) * K + lc;

    float acc[4][4] = {};
    for (int kt = 0; kt < K; kt += 16) {
        const float4 av = *(const float4*)(ag + kt);
        const float4 wv = *(const float4*)(wg + kt);
        As[lc + 0][lr] = av.x; As[lc + 1][lr] = av.y;
        As[lc + 2][lr] = av.z; As[lc + 3][lr] = av.w;
        Ws[lc + 0][lr] = wv.x; Ws[lc + 1][lr] = wv.y;
        Ws[lc + 2][lr] = wv.z; Ws[lc + 3][lr] = wv.w;
        __syncthreads();
#pragma unroll
        for (int kk = 0; kk < 16; kk++) {
            const float4 a = *(const float4*)&As[kk][ty << 2];
            const float4 w = *(const float4*)&Ws[kk][tx << 2];
            acc[0][0] += a.x * w.x; acc[0][1] += a.x * w.y; acc[0][2] += a.x * w.z; acc[0][3] += a.x * w.w;
            acc[1][0] += a.y * w.x; acc[1][1] += a.y * w.y; acc[1][2] += a.y * w.z; acc[1][3] += a.y * w.w;
            acc[2][0] += a.z * w.x; acc[2][1] += a.z * w.y; acc[2][2] += a.z * w.z; acc[2][3] += a.z * w.w;
            acc[3][0] += a.w * w.x; acc[3][1] += a.w * w.y; acc[3][2] += a.w * w.z; acc[3][3] += a.w * w.w;
        }
        __syncthreads();
    }

    float bv[4] = {0.f, 0.f, 0.f, 0.f};
    if (bias) {
        const float4 t4 = *(const float4*)(bias + bn + (tx << 2));
        bv[0] = t4.x; bv[1] = t4.y; bv[2] = t4.z; bv[3] = t4.w;
    }
#pragma unroll
    for (int i = 0; i < 4; i++) {
        const int r = bm + (ty << 2) + i;
        float4 o;
        o.x = acc[i][0] * alpha + bv[0];
        o.y = acc[i][1] * alpha + bv[1];
        o.z = acc[i][2] * alpha + bv[2];
        o.w = acc[i][3] * alpha + bv[3];
        if (Rsd) {
            const float4 rv = *(const float4*)(Rsd + (size_t)blockIdx.z * sC + (size_t)r * N + bn + (tx << 2));
            o.x += rv.x; o.y += rv.y; o.z += rv.z; o.w += rv.w;
        }
        if (relu) {
            o.x = fmaxf(o.x, 0.f); o.y = fmaxf(o.y, 0.f);
            o.z = fmaxf(o.z, 0.f); o.w = fmaxf(o.w, 0.f);
        }
        *(float4*)(Cb + (size_t)r * N + bn + (tx << 2)) = o;
    }
}

// ---------------------------------------------------------------------------
// C = A @ Bm (no transpose). A:[M,K] rm, Bm:[K,N] rm. Same tiling.
// ---------------------------------------------------------------------------
__global__ __launch_bounds__(256) void gemm_nn_k(
    const float* __restrict__ A, const float* __restrict__ Bm,
    float* __restrict__ C, int N, int K,
    size_t sA, size_t sB, size_t sC)
{
    __shared__ float As[16][64];
    __shared__ float Bs[16][64];
    const int tid = threadIdx.x;
    const int tx = tid & 15, ty = tid >> 4;
    const int bm = blockIdx.y * 64, bn = blockIdx.x * 64;
    const float* Ab = A + (size_t)blockIdx.z * sA;
    const float* Bb = Bm + (size_t)blockIdx.z * sB;
    float* Cb = C + (size_t)blockIdx.z * sC;

    const int lr = tid >> 2, lc = (tid & 3) << 2;      // A-tile mapping
    const int br = tid >> 4, bc = (tid & 15) << 2;     // B-tile mapping
    const float* ag = Ab + (size_t)(bm + lr) * K + lc;
    const float* bg = Bb + (size_t)br * N + bn + bc;

    float acc[4][4] = {};
    for (int kt = 0; kt < K; kt += 16) {
        const float4 av = *(const float4*)(ag + kt);
        const float4 bvv = *(const float4*)(bg + (size_t)kt * N);
        As[lc + 0][lr] = av.x; As[lc + 1][lr] = av.y;
        As[lc + 2][lr] = av.z; As[lc + 3][lr] = av.w;
        *(float4*)&Bs[br][bc] = bvv;
        __syncthreads();
#pragma unroll
        for (int kk = 0; kk < 16; kk++) {
            const float4 a = *(const float4*)&As[kk][ty << 2];
            const float4 w = *(const float4*)&Bs[kk][tx << 2];
            acc[0][0] += a.x * w.x; acc[0][1] += a.x * w.y; acc[0][2] += a.x * w.z; acc[0][3] += a.x * w.w;
            acc[1][0] += a.y * w.x; acc[1][1] += a.y * w.y; acc[1][2] += a.y * w.z; acc[1][3] += a.y * w.w;
            acc[2][0] += a.z * w.x; acc[2][1] += a.z * w.y; acc[2][2] += a.z * w.z; acc[2][3] += a.z * w.w;
            acc[3][0] += a.w * w.x; acc[3][1] += a.w * w.y; acc[3][2] += a.w * w.z; acc[3][3] += a.w * w.w;
        }
        __syncthreads();
    }
#pragma unroll
    for (int i = 0; i < 4; i++) {
        const int r = bm + (ty << 2) + i;
        float4 o;
        o.x = acc[i][0]; o.y = acc[i][1]; o.z = acc[i][2]; o.w = acc[i][3];
        *(float4*)(Cb + (size_t)r * N + bn + (tx << 2)) = o;
    }
}

// ---------------------------------------------------------------------------
// In-place row softmax, row length 1024. One block (256 thr) per row.
// ---------------------------------------------------------------------------
__global__ __launch_bounds__(256) void softmax_k(float* __restrict__ w) {
    const size_t row = blockIdx.x;
    float4* p = (float4*)(w + row * SEQ);
    const int t = threadIdx.x;
    float4 v = p[t];
    float m = fmaxf(fmaxf(v.x, v.y), fmaxf(v.z, v.w));
#pragma unroll
    for (int o = 16; o > 0; o >>= 1) m = fmaxf(m, __shfl_xor_sync(0xFFFFFFFFu, m, o));
    __shared__ float shm[8], shs[8];
    if ((t & 31) == 0) shm[t >> 5] = m;
    __syncthreads();
    float M = shm[0];
#pragma unroll
    for (int i = 1; i < 8; i++) M = fmaxf(M, shm[i]);
    float4 e;
    e.x = __expf(v.x - M) ; // fast exp: |err| ~2ulp, well under 1e-3 rel
    e.y = __expf(v.y - M);
    e.z = __expf(v.z - M);
    e.w = __expf(v.w - M);
    float s = e.x + e.y + e.z + e.w;
#pragma unroll
    for (int o = 16; o > 0; o >>= 1) s += __shfl_xor_sync(0xFFFFFFFFu, s, o);
    if ((t & 31) == 0) shs[t >> 5] = s;
    __syncthreads();
    float S = 0.f;
#pragma unroll
    for (int i = 0; i < 8; i++) S += shs[i];
    const float inv = 1.f / S;
    e.x *= inv; e.y *= inv; e.z *= inv; e.w *= inv;
    p[t] = e;
}

// ---------------------------------------------------------------------------
// logits[b,o] = dot(X[b,0,:], Wc[o,:]) + bc[o].  64 blocks of 256 threads.
// ---------------------------------------------------------------------------
__global__ __launch_bounds__(256) void cls_k(const float* __restrict__ X,
                                             const float* __restrict__ Wc,
                                             const float* __restrict__ bc,
                                             float* __restrict__ out) {
    const int b = blockIdx.x >> 1, o = blockIdx.x & 1;
    const int t = threadIdx.x;
    const float4 a = ((const float4*)(X + (size_t)b * SEQ * EMB))[t];
    const float4 w = ((const float4*)(Wc + (size_t)o * EMB))[t];
    float s = a.x * w.x + a.y * w.y + a.z * w.z + a.w * w.w;
#pragma unroll
    for (int off = 16; off > 0; off >>= 1) s += __shfl_xor_sync(0xFFFFFFFFu, s, off);
    __shared__ float sh[8];
    if ((t & 31) == 0) sh[t >> 5] = s;
    __syncthreads();
    if (t == 0) {
        float S = 0.f;
#pragma unroll
        for (int i = 0; i < 8; i++) S += sh[i];
        out[b * 2 + o] = S + bc[o];
    }
}

// ---------------------------------------------------------------------------
extern "C" void kernel_launch(void* const* d_in, const int* in_sizes, int n_in,
                              void* d_out, int out_size) {
    (void)in_sizes; (void)n_in; (void)out_size;
    const float* x     = (const float*)d_in[0];
    const float* pe    = (const float*)d_in[1];
    const float* ln1_g = (const float*)d_in[2];
    const float* ln1_b = (const float*)d_in[3];
    const float* Wq = (const float*)d_in[4];  const float* bq = (const float*)d_in[5];
    const float* Wk = (const float*)d_in[6];  const float* bk = (const float*)d_in[7];
    const float* Wv = (const float*)d_in[8];  const float* bv = (const float*)d_in[9];
    const float* Wo = (const float*)d_in[10]; const float* bo = (const float*)d_in[11];
    const float* ln2_g = (const float*)d_in[12];
    const float* ln2_b = (const float*)d_in[13];
    const float* W1 = (const float*)d_in[14]; const float* b1 = (const float*)d_in[15];
    const float* W2 = (const float*)d_in[16]; const float* b2 = (const float*)d_in[17];
    const float* Wc = (const float*)d_in[18]; const float* bc = (const float*)d_in[19];

    float* out = (float*)d_out;
    float* w1 = out + 64;
    float* w2 = w1 + NSS;

    float *px, *ph, *pq, *pk, *pv;
    cudaGetSymbolAddress((void**)&px, g_x);
    cudaGetSymbolAddress((void**)&ph, g_h);
    cudaGetSymbolAddress((void**)&pq, g_q);
    cudaGetSymbolAddress((void**)&pk, g_k);
    cudaGetSymbolAddress((void**)&pv, g_v);

    const size_t sSE = (size_t)SEQ * EMB;   // per-batch stride for q/k/v/h
    const size_t sSS = (size_t)SEQ * SEQ;   // per-batch stride for w

    // x1 = 32*x + pe
    embed_k<<<(unsigned)(NELEM / 4 / 256), 256>>>(x, pe, px);

    const dim3 gP(EMB / 64, NROWS / 64, 1);         // (16, 512)
    const dim3 gB(SEQ / 64, SEQ / 64, BATCH);       // (16, 16, 32)

    for (int blk = 0; blk < 2; blk++) {
        float* wout = blk ? w2 : w1;
        // h = LN1(x)
        ln_k<<<NROWS, 256>>>(px, ln1_g, ln1_b, ph);
        // q,k,v
        gemm_bt_k<<<gP, 256>>>(ph, Wq, bq, nullptr, pq, EMB, EMB, 0, 0, 0, 1.f, 0);
        gemm_bt_k<<<gP, 256>>>(ph, Wk, bk, nullptr, pk, EMB, EMB, 0, 0, 0, 1.f, 0);
        gemm_bt_k<<<gP, 256>>>(ph, Wv, bv, nullptr, pv, EMB, EMB, 0, 0, 0, 1.f, 0);
        // scores = q k^T / 32  (written straight into d_out region)
        gemm_bt_k<<<gB, 256>>>(pq, pk, nullptr, nullptr, wout, SEQ, EMB,
                               sSE, sSE, sSS, 0.03125f, 0);
        // softmax in place
        softmax_k<<<NROWS, 256>>>(wout);
        // attn = w @ v  -> h (reuse)
        gemm_nn_k<<<gB, 256>>>(wout, pv, ph, EMB, SEQ, sSS, sSE, sSE);
        // x2 = x + attn @ Wo^T + bo  -> q (reuse)
        gemm_bt_k<<<gP, 256>>>(ph, Wo, bo, px, pq, EMB, EMB, 0, 0, 0, 1.f, 0);
        // h = LN2(x2)
        ln_k<<<NROWS, 256>>>(pq, ln2_g, ln2_b, ph);
        // f1 = relu(h @ W1^T + b1) -> k (reuse)
        gemm_bt_k<<<gP, 256>>>(ph, W1, b1, nullptr, pk, FFD, EMB, 0, 0, 0, 1.f, 1);
        // x = x2 + f1 @ W2^T + b2
        gemm_bt_k<<<gP, 256>>>(pk, W2, b2, pq, px, EMB, FFD, 0, 0, 0, 1.f, 0);
    }

    // logits
    cls_k<<<64, 256>>>(px, Wc, bc, out);
}

// round 5
// speedup vs baseline: 1.0556x; 1.0556x over previous
#include <cuda_runtime.h>

// Problem constants
#define EMB   1024
#define SEQ   1024
#define BATCH 32
#define FFD   1024
#define NROWS (BATCH*SEQ)            // 32768
#define NELEM ((size_t)NROWS*EMB)    // 33554432
#define NSS   ((size_t)BATCH*SEQ*SEQ)// 33554432

// Scratch (allocation-free per harness rules)
__device__ float g_x[NELEM];   // running residual stream
__device__ float g_h[NELEM];   // LN output / attn result
__device__ float g_q[NELEM];   // q, later x2
__device__ float g_k[NELEM];   // k, later ff1 output
__device__ float g_v[NELEM];   // v

// ---------------------------------------------------------------------------
// x1 = 32*x + pe  (pe broadcast over batch)
// ---------------------------------------------------------------------------
__global__ __launch_bounds__(256) void embed_k(const float* __restrict__ x,
                                               const float* __restrict__ pe,
                                               float* __restrict__ o) {
    size_t i = (size_t)blockIdx.x * blockDim.x + threadIdx.x;  // float4 index
    const float4 a = ((const float4*)x)[i];
    const float4 p = ((const float4*)pe)[i & ((size_t)SEQ * EMB / 4 - 1)];
    float4 r;
    r.x = 32.f * a.x + p.x;
    r.y = 32.f * a.y + p.y;
    r.z = 32.f * a.z + p.z;
    r.w = 32.f * a.w + p.w;
    ((float4*)o)[i] = r;
}

// ---------------------------------------------------------------------------
// LayerNorm over last dim (1024). One block (256 thr) per row.
// ---------------------------------------------------------------------------
__global__ __launch_bounds__(256) void ln_k(const float* __restrict__ in,
                                            const float* __restrict__ g,
                                            const float* __restrict__ b,
                                            float* __restrict__ out) {
    const size_t row = blockIdx.x;
    const int t = threadIdx.x;
    const float4 v = ((const float4*)(in + row * EMB))[t];
    float s  = v.x + v.y + v.z + v.w;
    float ss = v.x * v.x + v.y * v.y + v.z * v.z + v.w * v.w;
#pragma unroll
    for (int o = 16; o > 0; o >>= 1) {
        s  += __shfl_xor_sync(0xFFFFFFFFu, s, o);
        ss += __shfl_xor_sync(0xFFFFFFFFu, ss, o);
    }
    __shared__ float sh_s[8], sh_ss[8];
    if ((t & 31) == 0) { sh_s[t >> 5] = s; sh_ss[t >> 5] = ss; }
    __syncthreads();
    float ts = 0.f, tss = 0.f;
#pragma unroll
    for (int i = 0; i < 8; i++) { ts += sh_s[i]; tss += sh_ss[i]; }
    const float mu  = ts * (1.f / EMB);
    const float var = tss * (1.f / EMB) - mu * mu;
    const float inv = rsqrtf(var + 1e-5f);
    const float4 gg = ((const float4*)g)[t];
    const float4 bb = ((const float4*)b)[t];
    float4 r;
    r.x = (v.x - mu) * inv * gg.x + bb.x;
    r.y = (v.y - mu) * inv * gg.y + bb.y;
    r.z = (v.z - mu) * inv * gg.z + bb.z;
    r.w = (v.w - mu) * inv * gg.w + bb.w;
    ((float4*)(out + row * EMB))[t] = r;
}

// ---------------------------------------------------------------------------
// C = alpha*(A @ W^T) [+bias] [+Rsd] [relu].  A:[M,K] rm, W:[N,K] rm.
// 64x64 tile, BK=16, 256 threads, 4x4 per thread. Batched via gridDim.z.
// ---------------------------------------------------------------------------
__global__ __launch_bounds__(256) void gemm_bt_k(
    const float* __restrict__ A, const float* __restrict__ W,
    const float* __restrict__ bias, const float* __restrict__ Rsd,
    float* __restrict__ C, int N, int K,
    size_t sA, size_t sW, size_t sC, float alpha, int relu)
{
    __shared__ float As[16][64];
    __shared__ float Ws[16][64];
    const int tid = threadIdx.x;
    const int tx = tid & 15, ty = tid >> 4;
    const int bm = blockIdx.y * 64, bn = blockIdx.x * 64;
    const float* Ab = A + (size_t)blockIdx.z * sA;
    const float* Wb = W + (size_t)blockIdx.z * sW;
    float* Cb = C + (size_t)blockIdx.z * sC;

    const int lr = tid >> 2, lc = (tid & 3) << 2;
    const float* ag = Ab + (size_t)(bm + lr) * K + lc;
    const float* wg = Wb + (size_t)(bn + lr) * K + lc;

    float acc[4][4] = {};
    for (int kt = 0; kt < K; kt += 16) {
        const float4 av = *(const float4*)(ag + kt);
        const float4 wv = *(const float4*)(wg + kt);
        As[lc + 0][lr] = av.x; As[lc + 1][lr] = av.y;
        As[lc + 2][lr] = av.z; As[lc + 3][lr] = av.w;
        Ws[lc + 0][lr] = wv.x; Ws[lc + 1][lr] = wv.y;
        Ws[lc + 2][lr] = wv.z; Ws[lc + 3][lr] = wv.w;
        __syncthreads();
#pragma unroll
        for (int kk = 0; kk < 16; kk++) {
            const float4 a = *(const float4*)&As[kk][ty << 2];
            const float4 w = *(const float4*)&Ws[kk][tx << 2];
            acc[0][0] += a.x * w.x; acc[0][1] += a.x * w.y; acc[0][2] += a.x * w.z; acc[0][3] += a.x * w.w;
            acc[1][0] += a.y * w.x; acc[1][1] += a.y * w.y; acc[1][2] += a.y * w.z; acc[1][3] += a.y * w.w;
            acc[2][0] += a.z * w.x; acc[2][1] += a.z * w.y; acc[2][2] += a.z * w.z; acc[2][3] += a.z * w.w;
            acc[3][0] += a.w * w.x; acc[3][1] += a.w * w.y; acc[3][2] += a.w * w.z; acc[3][3] += a.w * w.w;
        }
        __syncthreads();
    }

    float bv[4] = {0.f, 0.f, 0.f, 0.f};
    if (bias) {
        const float4 t4 = *(const float4*)(bias + bn + (tx << 2));
        bv[0] = t4.x; bv[1] = t4.y; bv[2] = t4.z; bv[3] = t4.w;
    }
#pragma unroll
    for (int i = 0; i < 4; i++) {
        const int r = bm + (ty << 2) + i;
        float4 o;
        o.x = acc[i][0] * alpha + bv[0];
        o.y = acc[i][1] * alpha + bv[1];
        o.z = acc[i][2] * alpha + bv[2];
        o.w = acc[i][3] * alpha + bv[3];
        if (Rsd) {
            const float4 rv = *(const float4*)(Rsd + (size_t)blockIdx.z * sC + (size_t)r * N + bn + (tx << 2));
            o.x += rv.x; o.y += rv.y; o.z += rv.z; o.w += rv.w;
        }
        if (relu) {
            o.x = fmaxf(o.x, 0.f); o.y = fmaxf(o.y, 0.f);
            o.z = fmaxf(o.z, 0.f); o.w = fmaxf(o.w, 0.f);
        }
        *(float4*)(Cb + (size_t)r * N + bn + (tx << 2)) = o;
    }
}

// ---------------------------------------------------------------------------
// C = A @ Bm (no transpose). A:[M,K] rm, Bm:[K,N] rm. Same tiling.
// ---------------------------------------------------------------------------
__global__ __launch_bounds__(256) void gemm_nn_k(
    const float* __restrict__ A, const float* __restrict__ Bm,
    float* __restrict__ C, int N, int K,
    size_t sA, size_t sB, size_t sC)
{
    __shared__ float As[16][64];
    __shared__ float Bs[16][64];
    const int tid = threadIdx.x;
    const int tx = tid & 15, ty = tid >> 4;
    const int bm = blockIdx.y * 64, bn = blockIdx.x * 64;
    const float* Ab = A + (size_t)blockIdx.z * sA;
    const float* Bb = Bm + (size_t)blockIdx.z * sB;
    float* Cb = C + (size_t)blockIdx.z * sC;

    const int lr = tid >> 2, lc = (tid & 3) << 2;      // A-tile mapping
    const int br = tid >> 4, bc = (tid & 15) << 2;     // B-tile mapping
    const float* ag = Ab + (size_t)(bm + lr) * K + lc;
    const float* bg = Bb + (size_t)br * N + bn + bc;

    float acc[4][4] = {};
    for (int kt = 0; kt < K; kt += 16) {
        const float4 av = *(const float4*)(ag + kt);
        const float4 bvv = *(const float4*)(bg + (size_t)kt * N);
        As[lc + 0][lr] = av.x; As[lc + 1][lr] = av.y;
        As[lc + 2][lr] = av.z; As[lc + 3][lr] = av.w;
        *(float4*)&Bs[br][bc] = bvv;
        __syncthreads();
#pragma unroll
        for (int kk = 0; kk < 16; kk++) {
            const float4 a = *(const float4*)&As[kk][ty << 2];
            const float4 w = *(const float4*)&Bs[kk][tx << 2];
            acc[0][0] += a.x * w.x; acc[0][1] += a.x * w.y; acc[0][2] += a.x * w.z; acc[0][3] += a.x * w.w;
            acc[1][0] += a.y * w.x; acc[1][1] += a.y * w.y; acc[1][2] += a.y * w.z; acc[1][3] += a.y * w.w;
            acc[2][0] += a.z * w.x; acc[2][1] += a.z * w.y; acc[2][2] += a.z * w.z; acc[2][3] += a.z * w.w;
            acc[3][0] += a.w * w.x; acc[3][1] += a.w * w.y; acc[3][2] += a.w * w.z; acc[3][3] += a.w * w.w;
        }
        __syncthreads();
    }
#pragma unroll
    for (int i = 0; i < 4; i++) {
        const int r = bm + (ty << 2) + i;
        float4 o;
        o.x = acc[i][0]; o.y = acc[i][1]; o.z = acc[i][2]; o.w = acc[i][3];
        *(float4*)(Cb + (size_t)r * N + bn + (tx << 2)) = o;
    }
}

// ---------------------------------------------------------------------------
// In-place row softmax, row length 1024. One block (256 thr) per row.
// ---------------------------------------------------------------------------
__global__ __launch_bounds__(256) void softmax_k(float* __restrict__ w) {
    const size_t row = blockIdx.x;
    float4* p = (float4*)(w + row * SEQ);
    const int t = threadIdx.x;
    float4 v = p[t];
    float m = fmaxf(fmaxf(v.x, v.y), fmaxf(v.z, v.w));
#pragma unroll
    for (int o = 16; o > 0; o >>= 1) m = fmaxf(m, __shfl_xor_sync(0xFFFFFFFFu, m, o));
    __shared__ float shm[8], shs[8];
    if ((t & 31) == 0) shm[t >> 5] = m;
    __syncthreads();
    float M = shm[0];
#pragma unroll
    for (int i = 1; i < 8; i++) M = fmaxf(M, shm[i]);
    float4 e;
    e.x = __expf(v.x - M) ; // fast exp: |err| ~2ulp, well under 1e-3 rel
    e.y = __expf(v.y - M);
    e.z = __expf(v.z - M);
    e.w = __expf(v.w - M);
    float s = e.x + e.y + e.z + e.w;
#pragma unroll
    for (int o = 16; o > 0; o >>= 1) s += __shfl_xor_sync(0xFFFFFFFFu, s, o);
    if ((t & 31) == 0) shs[t >> 5] = s;
    __syncthreads();
    float S = 0.f;
#pragma unroll
    for (int i = 0; i < 8; i++) S += shs[i];
    const float inv = 1.f / S;
    e.x *= inv; e.y *= inv; e.z *= inv; e.w *= inv;
    p[t] = e;
}

// ---------------------------------------------------------------------------
// logits[b,o] = dot(X[b,0,:], Wc[o,:]) + bc[o].  64 blocks of 256 threads.
// ---------------------------------------------------------------------------
__global__ __launch_bounds__(256) void cls_k(const float* __restrict__ X,
                                             const float* __restrict__ Wc,
                                             const float* __restrict__ bc,
                                             float* __restrict__ out) {
    const int b = blockIdx.x >> 1, o = blockIdx.x & 1;
    const int t = threadIdx.x;
    const float4 a = ((const float4*)(X + (size_t)b * SEQ * EMB))[t];
    const float4 w = ((const float4*)(Wc + (size_t)o * EMB))[t];
    float s = a.x * w.x + a.y * w.y + a.z * w.z + a.w * w.w;
#pragma unroll
    for (int off = 16; off > 0; off >>= 1) s += __shfl_xor_sync(0xFFFFFFFFu, s, off);
    __shared__ float sh[8];
    if ((t & 31) == 0) sh[t >> 5] = s;
    __syncthreads();
    if (t == 0) {
        float S = 0.f;
#pragma unroll
        for (int i = 0; i < 8; i++) S += sh[i];
        out[b * 2 + o] = S + bc[o];
    }
}

// ---------------------------------------------------------------------------
extern "C" void kernel_launch(void* const* d_in, const int* in_sizes, int n_in,
                              void* d_out, int out_size) {
    (void)in_sizes; (void)n_in; (void)out_size;
    const float* x     = (const float*)d_in[0];
    const float* pe    = (const float*)d_in[1];
    const float* ln1_g = (const float*)d_in[2];
    const float* ln1_b = (const float*)d_in[3];
    const float* Wq = (const float*)d_in[4];  const float* bq = (const float*)d_in[5];
    const float* Wk = (const float*)d_in[6];  const float* bk = (const float*)d_in[7];
    const float* Wv = (const float*)d_in[8];  const float* bv = (const float*)d_in[9];
    const float* Wo = (const float*)d_in[10]; const float* bo = (const float*)d_in[11];
    const float* ln2_g = (const float*)d_in[12];
    const float* ln2_b = (const float*)d_in[13];
    const float* W1 = (const float*)d_in[14]; const float* b1 = (const float*)d_in[15];
    const float* W2 = (const float*)d_in[16]; const float* b2 = (const float*)d_in[17];
    const float* Wc = (const float*)d_in[18]; const float* bc = (const float*)d_in[19];

    float* out = (float*)d_out;
    float* w1 = out + 64;
    float* w2 = w1 + NSS;

    float *px, *ph, *pq, *pk, *pv;
    cudaGetSymbolAddress((void**)&px, g_x);
    cudaGetSymbolAddress((void**)&ph, g_h);
    cudaGetSymbolAddress((void**)&pq, g_q);
    cudaGetSymbolAddress((void**)&pk, g_k);
    cudaGetSymbolAddress((void**)&pv, g_v);

    const size_t sSE = (size_t)SEQ * EMB;   // per-batch stride for q/k/v/h
    const size_t sSS = (size_t)SEQ * SEQ;   // per-batch stride for w

    // x1 = 32*x + pe
    embed_k<<<(unsigned)(NELEM / 4 / 256), 256>>>(x, pe, px);

    const dim3 gP(EMB / 64, NROWS / 64, 1);         // (16, 512)
    const dim3 gB(SEQ / 64, SEQ / 64, BATCH);       // (16, 16, 32)

    for (int blk = 0; blk < 2; blk++) {
        float* wout = blk ? w2 : w1;
        // h = LN1(x)
        ln_k<<<NROWS, 256>>>(px, ln1_g, ln1_b, ph);
        // q,k,v
        gemm_bt_k<<<gP, 256>>>(ph, Wq, bq, nullptr, pq, EMB, EMB, 0, 0, 0, 1.f, 0);
        gemm_bt_k<<<gP, 256>>>(ph, Wk, bk, nullptr, pk, EMB, EMB, 0, 0, 0, 1.f, 0);
        gemm_bt_k<<<gP, 256>>>(ph, Wv, bv, nullptr, pv, EMB, EMB, 0, 0, 0, 1.f, 0);
        // scores = q k^T / 32  (written straight into d_out region)
        gemm_bt_k<<<gB, 256>>>(pq, pk, nullptr, nullptr, wout, SEQ, EMB,
                               sSE, sSE, sSS, 0.03125f, 0);
        // softmax in place
        softmax_k<<<NROWS, 256>>>(wout);
        // attn = w @ v  -> h (reuse)
        gemm_nn_k<<<gB, 256>>>(wout, pv, ph, EMB, SEQ, sSS, sSE, sSE);
        // x2 = x + attn @ Wo^T + bo  -> q (reuse)
        gemm_bt_k<<<gP, 256>>>(ph, Wo, bo, px, pq, EMB, EMB, 0, 0, 0, 1.f, 0);
        // h = LN2(x2)
        ln_k<<<NROWS, 256>>>(pq, ln2_g, ln2_b, ph);
        // f1 = relu(h @ W1^T + b1) -> k (reuse)
        gemm_bt_k<<<gP, 256>>>(ph, W1, b1, nullptr, pk, FFD, EMB, 0, 0, 0, 1.f, 1);
        // x = x2 + f1 @ W2^T + b2
        gemm_bt_k<<<gP, 256>>>(pk, W2, b2, pq, px, EMB, FFD, 0, 0, 0, 1.f, 0);
    }

    // logits
    cls_k<<<64, 256>>>(px, Wc, bc, out);
}

// round 10
// speedup vs baseline: 2.9849x; 2.8277x over previous
#include <cuda_runtime.h>
#include <cuda_bf16.h>

#define EMB   1024
#define SEQ   1024
#define BATCH 32
#define KDIM  1024
#define NROWS (BATCH*SEQ)
#define NELEM ((size_t)NROWS*EMB)
#define NSS   ((size_t)BATCH*SEQ*SEQ)
#define WSZ   ((size_t)1024*1024)

// GEMM tiling
#define BM 128
#define BN 128
#define BK 32
#define NSTAGE 96        // 3 split phases x 32 K-chunks
#define LDS 40           // padded smem row stride (elements) for a 32-wide tile

// ---------------- PTX helpers (portable sm_80+ only) ----------------
__device__ __forceinline__ unsigned smem_u32(const void* p) {
    unsigned a;
    asm("{ .reg .u64 t; cvta.to.shared.u64 t, %1; cvt.u32.u64 %0, t; }" : "=r"(a) : "l"(p));
    return a;
}
#define CPASYNC16(dst, src) \
    asm volatile("cp.async.cg.shared.global [%0], [%1], 16;" :: "r"(dst), "l"(src))
#define CPCOMMIT() asm volatile("cp.async.commit_group;" ::: "memory")
#define CPWAIT(n)  asm volatile("cp.async.wait_group %0;" :: "n"(n) : "memory")
#define LDSM4(r0, r1, r2, r3, a) \
    asm volatile("ldmatrix.sync.aligned.m8n8.x4.shared.b16 {%0,%1,%2,%3}, [%4];" \
        : "=r"(r0), "=r"(r1), "=r"(r2), "=r"(r3) : "r"(a))
#define MMA(c, a, b) \
    asm volatile("mma.sync.aligned.m16n8k16.row.col.f32.bf16.bf16.f32 " \
        "{%0,%1,%2,%3}, {%4,%5,%6,%7}, {%8,%9}, {%0,%1,%2,%3};" \
        : "+f"((c)[0]), "+f"((c)[1]), "+f"((c)[2]), "+f"((c)[3]) \
        : "r"((a)[0]), "r"((a)[1]), "r"((a)[2]), "r"((a)[3]), "r"((b)[0]), "r"((b)[1]))

__device__ __forceinline__ void split2(float a, float b, __nv_bfloat162& h, __nv_bfloat162& l) {
    h.x = __float2bfloat16_rn(a); h.y = __float2bfloat16_rn(b);
    l.x = __float2bfloat16_rn(a - __bfloat162float(h.x));
    l.y = __float2bfloat16_rn(b - __bfloat162float(h.y));
}

// ---------------- scratch ----------------
__device__ float g_x[NELEM];                              // residual stream (fp32)
__device__ float g_y[NELEM];                              // x2 (fp32)
__device__ __nv_bfloat16 g_h_hi[NELEM],  g_h_lo[NELEM];
__device__ __nv_bfloat16 g_q_hi[NELEM],  g_q_lo[NELEM];
__device__ __nv_bfloat16 g_k_hi[NELEM],  g_k_lo[NELEM];
__device__ __nv_bfloat16 g_vT_hi[NELEM], g_vT_lo[NELEM];
__device__ __nv_bfloat16 g_w_hi[NSS],    g_w_lo[NSS];
__device__ __nv_bfloat16 g_W_hi[6*WSZ],  g_W_lo[6*WSZ];

// ---------------------------------------------------------------------------
// Tensor-core GEMM (legacy HMMA path): C = alpha*(A @ B^T) [+bias] [+Rsd] [relu]
// A:[M,1024], B:[N,1024], both hi/lo split bf16 (K-major). 3-product split via
// 96 pipeline stages: phase 0 (Ah,Bh), 1 (Ah,Bl), 2 (Al,Bh), all accumulated.
// grid = (N/128, M/128, Z). Outputs: optional fp32 Cf, optional split Ch/Cl
// (trans=1 stores C[r,e] at [(b*1024+e)*1024 + s], r = b*1024+s).
// ---------------------------------------------------------------------------
__global__ void __launch_bounds__(256, 2) gemm_mma(
    const __nv_bfloat16* __restrict__ Ah, const __nv_bfloat16* __restrict__ Al, size_t sA,
    const __nv_bfloat16* __restrict__ Bh, const __nv_bfloat16* __restrict__ Bl, size_t sB,
    const float* __restrict__ bias,
    const float* __restrict__ Rsd, size_t sR,
    float alpha, int relu,
    float* __restrict__ Cf,
    __nv_bfloat16* __restrict__ Ch, __nv_bfloat16* __restrict__ Cl,
    int trans, size_t sC)
{
    __shared__ __align__(16) __nv_bfloat16 As[2][BM * LDS];
    __shared__ __align__(16) __nv_bfloat16 Bs[2][BN * LDS];

    const int tid = threadIdx.x, wid = tid >> 5, lane = tid & 31;
    const int wm = wid & 3, wn = wid >> 2;          // warp grid 4(m) x 2(n)
    const int g = lane >> 2, tig = lane & 3;
    const int bm = blockIdx.y * BM, bn = blockIdx.x * BN;
    const int z = blockIdx.z;
    Ah += (size_t)z * sA;  Al += (size_t)z * sA;
    Bh += (size_t)z * sB;  Bl += (size_t)z * sB;

    const unsigned aB = smem_u32(As), bB = smem_u32(Bs);

    // staging: thread -> (row, 8-elem column group); 2 iters cover 128 rows
    const int srow = tid >> 2, sc = (tid & 3) * 8;
    // ldmatrix per-thread base offsets (bytes)
    const unsigned aoff0 = (unsigned)((wm * 32 + (lane & 15)) * LDS + (lane >> 4) * 8) * 2;
    const unsigned boff0 = (unsigned)((wn * 64 + (lane >> 4) * 8 + (lane & 7)) * LDS
                                      + ((lane >> 3) & 1) * 8) * 2;

    float acc[2][8][4];
#pragma unroll
    for (int a = 0; a < 2; a++)
#pragma unroll
        for (int b = 0; b < 8; b++)
#pragma unroll
            for (int c = 0; c < 4; c++) acc[a][b][c] = 0.f;

    auto stage = [&](int q, int buf) {
        const int ph = q >> 5;
        const int ko = (q & 31) * BK;
        const __nv_bfloat16* pA = (ph == 2) ? Al : Ah;
        const __nv_bfloat16* pB = (ph == 1) ? Bl : Bh;
#pragma unroll
        for (int i = 0; i < 2; i++) {
            const int row = srow + i * 64;
            const unsigned da = aB + buf * (BM * LDS * 2) + (unsigned)(row * LDS + sc) * 2;
            CPASYNC16(da, (const void*)(pA + (size_t)(bm + row) * KDIM + ko + sc));
            const unsigned db = bB + buf * (BN * LDS * 2) + (unsigned)(row * LDS + sc) * 2;
            CPASYNC16(db, (const void*)(pB + (size_t)(bn + row) * KDIM + ko + sc));
        }
    };

    auto compute = [&](int buf) {
#pragma unroll
        for (int ks = 0; ks < 2; ks++) {
            unsigned af[2][4];
#pragma unroll
            for (int mi = 0; mi < 2; mi++) {
                const unsigned ad = aB + buf * (BM * LDS * 2) + aoff0
                                    + (unsigned)(mi * 16 * LDS + ks * 16) * 2;
                LDSM4(af[mi][0], af[mi][1], af[mi][2], af[mi][3], ad);
            }
            unsigned bf[8][2];
#pragma unroll
            for (int jp = 0; jp < 4; jp++) {
                const unsigned bd = bB + buf * (BN * LDS * 2) + boff0
                                    + (unsigned)(jp * 16 * LDS + ks * 16) * 2;
                unsigned r0, r1, r2, r3;
                LDSM4(r0, r1, r2, r3, bd);
                bf[jp*2][0] = r0; bf[jp*2][1] = r1;
                bf[jp*2+1][0] = r2; bf[jp*2+1][1] = r3;
            }
#pragma unroll
            for (int mi = 0; mi < 2; mi++)
#pragma unroll
                for (int ni = 0; ni < 8; ni++)
                    MMA(acc[mi][ni], af[mi], bf[ni]);
        }
    };

    stage(0, 0); CPCOMMIT();
    for (int q = 0; q < NSTAGE; q++) {
        if (q + 1 < NSTAGE) { stage(q + 1, (q + 1) & 1); CPCOMMIT(); CPWAIT(1); }
        else               { CPWAIT(0); }
        __syncthreads();
        compute(q & 1);
        __syncthreads();
    }

    // ---- epilogue ----
#pragma unroll
    for (int mi = 0; mi < 2; mi++) {
#pragma unroll
        for (int half = 0; half < 2; half++) {
            const int r = bm + wm * 32 + mi * 16 + g + half * 8;
#pragma unroll
            for (int ni = 0; ni < 8; ni++) {
                const int cc = bn + wn * 64 + ni * 8 + tig * 2;
                float v0 = acc[mi][ni][half * 2 + 0] * alpha;
                float v1 = acc[mi][ni][half * 2 + 1] * alpha;
                if (bias) { v0 += __ldg(bias + cc); v1 += __ldg(bias + cc + 1); }
                if (Rsd) {
                    const float2 rv = *(const float2*)(Rsd + (size_t)z * sR
                                                       + (size_t)r * 1024 + cc);
                    v0 += rv.x; v1 += rv.y;
                }
                if (relu) { v0 = fmaxf(v0, 0.f); v1 = fmaxf(v1, 0.f); }
                if (Cf)
                    *(float2*)(Cf + (size_t)z * sC + (size_t)r * 1024 + cc)
                        = make_float2(v0, v1);
                if (Ch) {
                    if (!trans) {
                        __nv_bfloat162 h2, l2;
                        split2(v0, v1, h2, l2);
                        *(__nv_bfloat162*)(Ch + (size_t)z * sC + (size_t)r * 1024 + cc) = h2;
                        *(__nv_bfloat162*)(Cl + (size_t)z * sC + (size_t)r * 1024 + cc) = l2;
                    } else {
                        const size_t b = (size_t)r >> 10, s5 = (size_t)r & 1023;
                        const size_t i0 = ((b << 10) + (size_t)cc)     * 1024 + s5;
                        const size_t i1 = ((b << 10) + (size_t)cc + 1) * 1024 + s5;
                        __nv_bfloat16 h0 = __float2bfloat16_rn(v0);
                        Ch[i0] = h0; Cl[i0] = __float2bfloat16_rn(v0 - __bfloat162float(h0));
                        __nv_bfloat16 h1 = __float2bfloat16_rn(v1);
                        Ch[i1] = h1; Cl[i1] = __float2bfloat16_rn(v1 - __bfloat162float(h1));
                    }
                }
            }
        }
    }
}

// ---------------------------------------------------------------------------
__global__ __launch_bounds__(256) void embed_k(const float* __restrict__ x,
                                               const float* __restrict__ pe,
                                               float* __restrict__ o) {
    size_t i = (size_t)blockIdx.x * 256 + threadIdx.x;
    const float4 a = ((const float4*)x)[i];
    const float4 p = ((const float4*)pe)[i & ((size_t)SEQ * EMB / 4 - 1)];
    ((float4*)o)[i] = make_float4(32.f*a.x+p.x, 32.f*a.y+p.y, 32.f*a.z+p.z, 32.f*a.w+p.w);
}

__global__ __launch_bounds__(256) void split_k(const float* __restrict__ in,
                                               __nv_bfloat16* __restrict__ oh,
                                               __nv_bfloat16* __restrict__ ol) {
    size_t i = ((size_t)blockIdx.x * 256 + threadIdx.x) * 4;
    float4 v = *(const float4*)(in + i);
    __nv_bfloat162 h0, l0, h1, l1;
    split2(v.x, v.y, h0, l0); split2(v.z, v.w, h1, l1);
    *(__nv_bfloat162*)(oh + i)     = h0; *(__nv_bfloat162*)(oh + i + 2) = h1;
    *(__nv_bfloat162*)(ol + i)     = l0; *(__nv_bfloat162*)(ol + i + 2) = l1;
}

__global__ __launch_bounds__(256) void ln_split_k(const float* __restrict__ in,
                                                  const float* __restrict__ g,
                                                  const float* __restrict__ b,
                                                  __nv_bfloat16* __restrict__ oh,
                                                  __nv_bfloat16* __restrict__ ol) {
    const size_t row = blockIdx.x;
    const int t = threadIdx.x;
    const float4 v = ((const float4*)(in + row * EMB))[t];
    float s  = v.x + v.y + v.z + v.w;
    float ss = v.x*v.x + v.y*v.y + v.z*v.z + v.w*v.w;
#pragma unroll
    for (int o = 16; o > 0; o >>= 1) {
        s  += __shfl_xor_sync(0xFFFFFFFFu, s, o);
        ss += __shfl_xor_sync(0xFFFFFFFFu, ss, o);
    }
    __shared__ float sh_s[8], sh_ss[8];
    if ((t & 31) == 0) { sh_s[t >> 5] = s; sh_ss[t >> 5] = ss; }
    __syncthreads();
    float ts = 0.f, tss = 0.f;
#pragma unroll
    for (int i = 0; i < 8; i++) { ts += sh_s[i]; tss += sh_ss[i]; }
    const float mu  = ts * (1.f / EMB);
    const float inv = rsqrtf(tss * (1.f / EMB) - mu * mu + 1e-5f);
    const float4 gg = ((const float4*)g)[t];
    const float4 bb = ((const float4*)b)[t];
    float r0 = (v.x - mu) * inv * gg.x + bb.x;
    float r1 = (v.y - mu) * inv * gg.y + bb.y;
    float r2 = (v.z - mu) * inv * gg.z + bb.z;
    float r3 = (v.w - mu) * inv * gg.w + bb.w;
    size_t o4 = row * EMB + (size_t)t * 4;
    __nv_bfloat162 h0, l0, h1, l1;
    split2(r0, r1, h0, l0); split2(r2, r3, h1, l1);
    *(__nv_bfloat162*)(oh + o4)     = h0; *(__nv_bfloat162*)(oh + o4 + 2) = h1;
    *(__nv_bfloat162*)(ol + o4)     = l0; *(__nv_bfloat162*)(ol + o4 + 2) = l1;
}

__global__ __launch_bounds__(256) void softmax_k(float* __restrict__ w,
                                                 __nv_bfloat16* __restrict__ oh,
                                                 __nv_bfloat16* __restrict__ ol) {
    const size_t row = blockIdx.x;
    float4* p = (float4*)(w + row * SEQ);
    const int t = threadIdx.x;
    float4 v = p[t];
    float m = fmaxf(fmaxf(v.x, v.y), fmaxf(v.z, v.w));
#pragma unroll
    for (int o = 16; o > 0; o >>= 1) m = fmaxf(m, __shfl_xor_sync(0xFFFFFFFFu, m, o));
    __shared__ float shm[8], shs[8];
    if ((t & 31) == 0) shm[t >> 5] = m;
    __syncthreads();
    float M = shm[0];
#pragma unroll
    for (int i = 1; i < 8; i++) M = fmaxf(M, shm[i]);
    float4 e;
    e.x = __expf(v.x - M); e.y = __expf(v.y - M);
    e.z = __expf(v.z - M); e.w = __expf(v.w - M);
    float s = e.x + e.y + e.z + e.w;
#pragma unroll
    for (int o = 16; o > 0; o >>= 1) s += __shfl_xor_sync(0xFFFFFFFFu, s, o);
    if ((t & 31) == 0) shs[t >> 5] = s;
    __syncthreads();
    float S = 0.f;
#pragma unroll
    for (int i = 0; i < 8; i++) S += shs[i];
    const float inv = 1.f / S;
    e.x *= inv; e.y *= inv; e.z *= inv; e.w *= inv;
    p[t] = e;
    size_t o4 = row * SEQ + (size_t)t * 4;
    __nv_bfloat162 h0, l0, h1, l1;
    split2(e.x, e.y, h0, l0); split2(e.z, e.w, h1, l1);
    *(__nv_bfloat162*)(oh + o4)     = h0; *(__nv_bfloat162*)(oh + o4 + 2) = h1;
    *(__nv_bfloat162*)(ol + o4)     = l0; *(__nv_bfloat162*)(ol + o4 + 2) = l1;
}

__global__ __launch_bounds__(256) void cls_k(const float* __restrict__ X,
                                             const float* __restrict__ Wc,
                                             const float* __restrict__ bc,
                                             float* __restrict__ out) {
    const int b = blockIdx.x >> 1, o = blockIdx.x & 1;
    const int t = threadIdx.x;
    const float4 a = ((const float4*)(X + (size_t)b * SEQ * EMB))[t];
    const float4 w = ((const float4*)(Wc + (size_t)o * EMB))[t];
    float s = a.x*w.x + a.y*w.y + a.z*w.z + a.w*w.w;
#pragma unroll
    for (int off = 16; off > 0; off >>= 1) s += __shfl_xor_sync(0xFFFFFFFFu, s, off);
    __shared__ float sh[8];
    if ((t & 31) == 0) sh[t >> 5] = s;
    __syncthreads();
    if (t == 0) {
        float S = 0.f;
#pragma unroll
        for (int i = 0; i < 8; i++) S += sh[i];
        out[b * 2 + o] = S + bc[o];
    }
}

// ---------------------------------------------------------------------------
extern "C" void kernel_launch(void* const* d_in, const int* in_sizes, int n_in,
                              void* d_out, int out_size) {
    (void)in_sizes; (void)n_in; (void)out_size;
    const float* x     = (const float*)d_in[0];
    const float* pe    = (const float*)d_in[1];
    const float* ln1_g = (const float*)d_in[2];
    const float* ln1_b = (const float*)d_in[3];
    const float* Wq = (const float*)d_in[4];  const float* bq = (const float*)d_in[5];
    const float* Wk = (const float*)d_in[6];  const float* bk = (const float*)d_in[7];
    const float* Wv = (const float*)d_in[8];  const float* bv = (const float*)d_in[9];
    const float* Wo = (const float*)d_in[10]; const float* bo = (const float*)d_in[11];
    const float* ln2_g = (const float*)d_in[12];
    const float* ln2_b = (const float*)d_in[13];
    const float* W1 = (const float*)d_in[14]; const float* b1 = (const float*)d_in[15];
    const float* W2 = (const float*)d_in[16]; const float* b2 = (const float*)d_in[17];
    const float* Wc = (const float*)d_in[18]; const float* bc = (const float*)d_in[19];

    float* out = (float*)d_out;
    float* w1 = out + 64;
    float* w2 = w1 + NSS;

    float *px, *py;
    __nv_bfloat16 *hh, *hl, *qh, *ql, *kh, *kl, *vh, *vl, *wh, *wl, *Wh, *Wl;
    cudaGetSymbolAddress((void**)&px, g_x);
    cudaGetSymbolAddress((void**)&py, g_y);
    cudaGetSymbolAddress((void**)&hh, g_h_hi);  cudaGetSymbolAddress((void**)&hl, g_h_lo);
    cudaGetSymbolAddress((void**)&qh, g_q_hi);  cudaGetSymbolAddress((void**)&ql, g_q_lo);
    cudaGetSymbolAddress((void**)&kh, g_k_hi);  cudaGetSymbolAddress((void**)&kl, g_k_lo);
    cudaGetSymbolAddress((void**)&vh, g_vT_hi); cudaGetSymbolAddress((void**)&vl, g_vT_lo);
    cudaGetSymbolAddress((void**)&wh, g_w_hi);  cudaGetSymbolAddress((void**)&wl, g_w_lo);
    cudaGetSymbolAddress((void**)&Wh, g_W_hi);  cudaGetSymbolAddress((void**)&Wl, g_W_lo);

    const size_t sSE = (size_t)SEQ * EMB;
    const size_t sSS = (size_t)SEQ * SEQ;

    // weight splits (Wq,Wk,Wv,Wo,W1,W2)
    const float* Ws[6] = {Wq, Wk, Wv, Wo, W1, W2};
    for (int i = 0; i < 6; i++)
        split_k<<<1024, 256>>>(Ws[i], Wh + (size_t)i * WSZ, Wl + (size_t)i * WSZ);
    __nv_bfloat16 *Wqh = Wh,         *Wql = Wl;
    __nv_bfloat16 *Wkh = Wh + WSZ,   *Wkl = Wl + WSZ;
    __nv_bfloat16 *Wvh = Wh + 2*WSZ, *Wvl = Wl + 2*WSZ;
    __nv_bfloat16 *Woh = Wh + 3*WSZ, *Wol = Wl + 3*WSZ;
    __nv_bfloat16 *W1h = Wh + 4*WSZ, *W1l = Wl + 4*WSZ;
    __nv_bfloat16 *W2h = Wh + 5*WSZ, *W2l = Wl + 5*WSZ;

    // x1 = 32*x + pe
    embed_k<<<(unsigned)(NELEM / 4 / 256), 256>>>(x, pe, px);

    const dim3 gP(EMB / BN, NROWS / BM, 1);     // (8, 256, 1)
    const dim3 gB(SEQ / BN, SEQ / BM, BATCH);   // (8, 8, 32)

    for (int blk = 0; blk < 2; blk++) {
        float* wout = blk ? w2 : w1;
        // h = LN1(x) (split)
        ln_split_k<<<NROWS, 256>>>(px, ln1_g, ln1_b, hh, hl);
        // q = h@Wq^T + bq (split)
        gemm_mma<<<gP, 256>>>(hh, hl, 0, Wqh, Wql, 0, bq, nullptr, 0, 1.f, 0,
                              nullptr, qh, ql, 0, 0);
        // k
        gemm_mma<<<gP, 256>>>(hh, hl, 0, Wkh, Wkl, 0, bk, nullptr, 0, 1.f, 0,
                              nullptr, kh, kl, 0, 0);
        // v (transposed split: vT[b,e,s])
        gemm_mma<<<gP, 256>>>(hh, hl, 0, Wvh, Wvl, 0, bv, nullptr, 0, 1.f, 0,
                              nullptr, vh, vl, 1, 0);
        // scores = q k^T / 32 -> fp32 wout (straight into d_out region)
        gemm_mma<<<gB, 256>>>(qh, ql, sSE, kh, kl, sSE, nullptr, nullptr, 0,
                              0.03125f, 0, wout, nullptr, nullptr, 0, sSS);
        // softmax in place + split
        softmax_k<<<NROWS, 256>>>(wout, wh, wl);
        // attn = w @ vT^T -> split into h (reuse)
        gemm_mma<<<gB, 256>>>(wh, wl, sSS, vh, vl, sSE, nullptr, nullptr, 0,
                              1.f, 0, nullptr, hh, hl, 0, sSE);
        // x2 = x1 + attn@Wo^T + bo -> fp32 py
        gemm_mma<<<gP, 256>>>(hh, hl, 0, Woh, Wol, 0, bo, px, 0, 1.f, 0,
                              py, nullptr, nullptr, 0, 0);
        // h = LN2(x2) (split)
        ln_split_k<<<NROWS, 256>>>(py, ln2_g, ln2_b, hh, hl);
        // f1 = relu(h@W1^T + b1) -> split into q (reuse)
        gemm_mma<<<gP, 256>>>(hh, hl, 0, W1h, W1l, 0, b1, nullptr, 0, 1.f, 1,
                              nullptr, qh, ql, 0, 0);
        // x3 = x2 + f1@W2^T + b2 -> fp32 px
        gemm_mma<<<gP, 256>>>(qh, ql, 0, W2h, W2l, 0, b2, py, 0, 1.f, 0,
                              px, nullptr, nullptr, 0, 0);
    }

    cls_k<<<64, 256>>>(px, Wc, bc, out);
}